// round 1
// baseline (speedup 1.0000x reference)
#include <cuda_runtime.h>

// GCN 2-layer, GB300. Algebra: per-edge payload reduced to float2 by factoring
// W and dinv_dst out of the edge sum:
//   u[i]    = sum_{j->i} (x_j * dinv_j)                (edge pass, 8B payload)
//   agg1[i] = (u[i] * dinv_i) @ W1
//   out1    = relu(agg1 + (x@W1)/deg + b1)
//   h2      = out1 @ W2   (2-wide)
//   u2[i]   = sum_{j->i} (h2_j * dinv_j)
//   out[i]  = u2[i]*dinv_i + h2_i/deg_i + b2

#define NN 200000
#define NE 12800000

__device__ float  d_deg [NN];
__device__ float  d_dinv[NN];
__device__ float2 d_g   [NN];   // per-node gather payload (x*dinv, then h2*dinv)
__device__ float2 d_u   [NN];   // per-node accumulator
__device__ float2 d_h2  [NN];

__device__ __forceinline__ void red_add_f32(float* p, float v) {
    asm volatile("red.global.add.f32 [%0], %1;" :: "l"(p), "f"(v) : "memory");
}
__device__ __forceinline__ void red_add_v2f32(float2* p, float x, float y) {
    asm volatile("red.global.add.v2.f32 [%0], {%1, %2};"
                 :: "l"(p), "f"(x), "f"(y) : "memory");
}

// ---------------- node kernels ----------------

__global__ void k_init() {
    int i = blockIdx.x * blockDim.x + threadIdx.x;
    if (i < NN) {
        d_deg[i] = 1.0f;                  // self-loop
        d_u[i]   = make_float2(0.f, 0.f);
    }
}

__global__ void k_nodeA(const float2* __restrict__ x) {
    int i = blockIdx.x * blockDim.x + threadIdx.x;
    if (i < NN) {
        float dinv = rsqrtf(d_deg[i]);
        d_dinv[i] = dinv;
        float2 xv = x[i];
        d_g[i] = make_float2(xv.x * dinv, xv.y * dinv);
    }
}

__global__ void k_nodeB(const float2* __restrict__ x,
                        const float*  __restrict__ W1,   // [2,16] row-major
                        const float*  __restrict__ b1,   // [16]
                        const float*  __restrict__ W2) { // [16,2] row-major
    int i = blockIdx.x * blockDim.x + threadIdx.x;
    if (i >= NN) return;
    float dinv = d_dinv[i];
    float idg  = dinv * dinv;            // 1/deg
    float2 xv  = x[i];
    float2 u   = d_u[i];
    // combined coefficient on W1 rows: s1 + x*(1/deg)
    float ax = u.x * dinv + xv.x * idg;
    float ay = u.y * dinv + xv.y * idg;
    float h20 = 0.f, h21 = 0.f;
#pragma unroll
    for (int f = 0; f < 16; f++) {
        float a = fmaf(ax, __ldg(&W1[f]), fmaf(ay, __ldg(&W1[16 + f]), __ldg(&b1[f])));
        a = fmaxf(a, 0.f);               // relu
        h20 = fmaf(a, __ldg(&W2[2 * f]),     h20);
        h21 = fmaf(a, __ldg(&W2[2 * f + 1]), h21);
    }
    d_h2[i] = make_float2(h20, h21);
    d_g[i]  = make_float2(h20 * dinv, h21 * dinv);
    d_u[i]  = make_float2(0.f, 0.f);     // re-zero for layer-2 edge pass
}

__global__ void k_nodeC(const float* __restrict__ b2, float2* __restrict__ out) {
    int i = blockIdx.x * blockDim.x + threadIdx.x;
    if (i >= NN) return;
    float dinv = d_dinv[i];
    float idg  = dinv * dinv;
    float2 u  = d_u[i];
    float2 h2 = d_h2[i];
    out[i] = make_float2(fmaf(u.x, dinv, fmaf(h2.x, idg, __ldg(&b2[0]))),
                         fmaf(u.y, dinv, fmaf(h2.y, idg, __ldg(&b2[1]))));
}

// ---------------- edge kernels ----------------

// degree histogram: 4 edges/thread, vectorized dst load
__global__ void k_deg(const int4* __restrict__ dst4) {
    int i = blockIdx.x * blockDim.x + threadIdx.x;   // i < NE/4
    int4 d = __ldg(&dst4[i]);
    red_add_f32(&d_deg[d.x], 1.0f);
    red_add_f32(&d_deg[d.y], 1.0f);
    red_add_f32(&d_deg[d.z], 1.0f);
    red_add_f32(&d_deg[d.w], 1.0f);
}

// u[dst] += g[src] : 4 edges/thread, gathers issued before atomics for MLP
__global__ void k_edge(const int4* __restrict__ src4,
                       const int4* __restrict__ dst4) {
    int i = blockIdx.x * blockDim.x + threadIdx.x;   // i < NE/4
    int4 s = __ldg(&src4[i]);
    int4 d = __ldg(&dst4[i]);
    float2 g0 = __ldg(&d_g[s.x]);
    float2 g1 = __ldg(&d_g[s.y]);
    float2 g2 = __ldg(&d_g[s.z]);
    float2 g3 = __ldg(&d_g[s.w]);
    red_add_v2f32(&d_u[d.x], g0.x, g0.y);
    red_add_v2f32(&d_u[d.y], g1.x, g1.y);
    red_add_v2f32(&d_u[d.z], g2.x, g2.y);
    red_add_v2f32(&d_u[d.w], g3.x, g3.y);
}

// ---------------- launch ----------------

extern "C" void kernel_launch(void* const* d_in, const int* in_sizes, int n_in,
                              void* d_out, int out_size) {
    // metadata order: x, W1, b1, W2, b2, edge_index
    const float2* x  = (const float2*)d_in[0];
    const float*  W1 = (const float*) d_in[1];
    const float*  b1 = (const float*) d_in[2];
    const float*  W2 = (const float*) d_in[3];
    const float*  b2 = (const float*) d_in[4];
    const int*    ei = (const int*)   d_in[5];   // [2, NE] row-major
    const int4*   src4 = (const int4*)(ei);
    const int4*   dst4 = (const int4*)(ei + NE);
    float2* out = (float2*)d_out;

    const int NT = 256;
    const int nodeBlocks = (NN + NT - 1) / NT;
    const int edgeBlocks = (NE / 4) / NT;            // 12.8M divisible by 1024

    k_init <<<nodeBlocks, NT>>>();
    k_deg  <<<edgeBlocks, NT>>>(dst4);
    k_nodeA<<<nodeBlocks, NT>>>(x);
    k_edge <<<edgeBlocks, NT>>>(src4, dst4);
    k_nodeB<<<nodeBlocks, NT>>>(x, W1, b1, W2);
    k_edge <<<edgeBlocks, NT>>>(src4, dst4);
    k_nodeC<<<nodeBlocks, NT>>>(b2, out);
}